// round 1
// baseline (speedup 1.0000x reference)
#include <cuda_runtime.h>
#include <cstdint>
#include <cstddef>

// Problem constants (fixed by the dataset)
#define Bc 32
#define Sc 1024
#define Hc 1024
#define Wc 128
#define Kc 6
#define NHc 16
#define HDc 64
#define Lc (Bc*Wc)        // 4096 groups
#define Mc (Lc*Kc)        // 24576 projected rows
#define Nc (2*Hc)         // 2048 output features (q|k)

// qk scratch: 24576 x 2048 fp32 = 201 MB (static device array: allocation-free)
__device__ float g_qk[(size_t)Mc * Nc];

// ---------------------------------------------------------------------------
// GEMM: qk[m, n] = sum_h x[m,h] * W[n,h] + bias[n]
//   x[m,:] = mask(m) ? emb[b, idx[m], :] : 0
// tf32 mma.sync m16n8k8, 128x128 block tile, BK=16, double-buffered cp.async
// ---------------------------------------------------------------------------
#define BM 128
#define BN 128
#define BK 16
#define AST 20   // smem row stride (floats): BK + 4 pad, 16B-aligned rows

__device__ __forceinline__ uint32_t f2tf(float x) {
    uint32_t u;
    asm("cvt.rna.tf32.f32 %0, %1;" : "=r"(u) : "f"(x));
    return u;
}

__device__ __forceinline__ void mma8(float* c, const uint32_t* a, const uint32_t* b) {
    asm volatile(
        "mma.sync.aligned.m16n8k8.row.col.f32.tf32.tf32.f32 "
        "{%0,%1,%2,%3}, {%4,%5,%6,%7}, {%8,%9}, {%0,%1,%2,%3};\n"
        : "+f"(c[0]), "+f"(c[1]), "+f"(c[2]), "+f"(c[3])
        : "r"(a[0]), "r"(a[1]), "r"(a[2]), "r"(a[3]), "r"(b[0]), "r"(b[1]));
}

__device__ __forceinline__ void load_tiles(
    float* dA, float* dB,
    const float* const* s_ap, const int* s_am,
    const float* bbase, int kt, int tid)
{
    // A: 128 rows x 16 floats = 512 float4 chunks
    #pragma unroll
    for (int i = tid; i < (BM*BK/4); i += 256) {
        int row = i >> 2, q = i & 3;
        const float* src = s_ap[row] + kt*BK + q*4;
        uint32_t da = (uint32_t)__cvta_generic_to_shared(dA + row*AST + q*4);
        int sz = s_am[row] ? 16 : 0;   // masked rows -> zero-fill
        asm volatile("cp.async.cg.shared.global [%0], [%1], 16, %2;\n"
                     :: "r"(da), "l"(src), "r"(sz));
    }
    // B: 128 weight rows x 16 floats
    #pragma unroll
    for (int i = tid; i < (BM*BK/4); i += 256) {
        int row = i >> 2, q = i & 3;
        const float* src = bbase + (size_t)row*Hc + kt*BK + q*4;
        uint32_t db = (uint32_t)__cvta_generic_to_shared(dB + row*AST + q*4);
        asm volatile("cp.async.cg.shared.global [%0], [%1], 16;\n"
                     :: "r"(db), "l"(src));
    }
    asm volatile("cp.async.commit_group;\n" ::);
}

__global__ __launch_bounds__(256, 2)
void gemm_qk(const float* __restrict__ emb, const float* __restrict__ wqk,
             const float* __restrict__ bias, const int* __restrict__ sidx)
{
    __shared__ float sA[2][BM*AST];
    __shared__ float sB[2][BM*AST];
    __shared__ const float* s_ap[BM];
    __shared__ int s_am[BM];

    const int tid = threadIdx.x;
    const int bx = blockIdx.x;   // N tile (0..15)
    const int by = blockIdx.y;   // M tile (0..191)

    if (tid < BM) {
        int m = by*BM + tid;
        int g = m / 6;
        int kk = m - g*6;
        int idxv = sidx[m];
        int b = g >> 7;                           // g / Wc
        int valid = (kk == 0) || (idxv != 0);     // reconstructed mask
        s_ap[tid] = emb + ((size_t)(b*Sc + idxv)) * Hc;
        s_am[tid] = valid;
    }
    __syncthreads();

    const float* bbase = wqk + (size_t)(bx*BN) * Hc;

    const int wid = tid >> 5;
    const int lane = tid & 31;
    const int warp_m = wid & 3;    // 4 warps over M (32 rows each)
    const int warp_n = wid >> 2;   // 2 warps over N (64 cols each)
    const int gid = lane >> 2;
    const int tig = lane & 3;

    float c[2][8][4] = {};

    const int NT = Hc / BK;   // 64 k-tiles
    load_tiles(sA[0], sB[0], s_ap, s_am, bbase, 0, tid);

    for (int kt = 0; kt < NT; kt++) {
        int sel = kt & 1;
        if (kt + 1 < NT) {
            load_tiles(sA[sel^1], sB[sel^1], s_ap, s_am, bbase, kt+1, tid);
            asm volatile("cp.async.wait_group %0;\n" :: "n"(1));
        } else {
            asm volatile("cp.async.wait_group %0;\n" :: "n"(0));
        }
        __syncthreads();

        const float* As = sA[sel];
        const float* Bs = sB[sel];
        #pragma unroll
        for (int ks = 0; ks < BK; ks += 8) {
            uint32_t af[2][4];
            #pragma unroll
            for (int mf = 0; mf < 2; mf++) {
                int r0 = warp_m*32 + mf*16;
                af[mf][0] = f2tf(As[(r0+gid  )*AST + ks + tig    ]);
                af[mf][1] = f2tf(As[(r0+gid+8)*AST + ks + tig    ]);
                af[mf][2] = f2tf(As[(r0+gid  )*AST + ks + tig + 4]);
                af[mf][3] = f2tf(As[(r0+gid+8)*AST + ks + tig + 4]);
            }
            uint32_t bf[8][2];
            #pragma unroll
            for (int nf = 0; nf < 8; nf++) {
                int c0 = warp_n*64 + nf*8;
                bf[nf][0] = f2tf(Bs[(c0+gid)*AST + ks + tig    ]);
                bf[nf][1] = f2tf(Bs[(c0+gid)*AST + ks + tig + 4]);
            }
            #pragma unroll
            for (int mf = 0; mf < 2; mf++)
                #pragma unroll
                for (int nf = 0; nf < 8; nf++)
                    mma8(c[mf][nf], af[mf], bf[nf]);
        }
        __syncthreads();
    }

    // Epilogue: bias add + store
    #pragma unroll
    for (int mf = 0; mf < 2; mf++) {
        #pragma unroll
        for (int nf = 0; nf < 8; nf++) {
            int row = by*BM + warp_m*32 + mf*16 + gid;
            int col = bx*BN + warp_n*64 + nf*8 + tig*2;
            float b0 = bias[col], b1 = bias[col+1];
            float2 v0 = make_float2(c[mf][nf][0] + b0, c[mf][nf][1] + b1);
            float2 v1 = make_float2(c[mf][nf][2] + b0, c[mf][nf][3] + b1);
            *(float2*)&g_qk[(size_t)row*Nc + col]     = v0;
            *(float2*)&g_qk[(size_t)(row+8)*Nc + col] = v1;
        }
    }
}

// ---------------------------------------------------------------------------
// Copy/zero: out row s (window w=s/8, slot k=s%8):
//   k in [1,6) and idx!=0 -> zeros (merged-away token)
//   otherwise            -> copy (k==0 rows are overwritten by attn_merge)
// ---------------------------------------------------------------------------
__global__ __launch_bounds__(256)
void copy_zero(const float* __restrict__ emb, const int* __restrict__ sidx,
               float* __restrict__ out)
{
    int row = blockIdx.x;        // 0 .. B*S-1
    int b = row >> 10;
    int s = row & 1023;
    int w = s >> 3;
    int k = s & 7;
    int zero = 0;
    if (k >= 1 && k < 6) {
        int iv = __ldg(&sidx[(b*Wc + w)*Kc + k]);
        zero = (iv != 0);
    }
    const float4* src = (const float4*)(emb + (size_t)row * Hc);
    float4* dst = (float4*)(out + (size_t)row * Hc);
    float4 v = src[threadIdx.x];
    if (zero) v = make_float4(0.f, 0.f, 0.f, 0.f);
    dst[threadIdx.x] = v;
}

// ---------------------------------------------------------------------------
// Attention + merge: one block per group g. Stages the group's 6x2048 qk slab
// (48 KB, contiguous in g_qk) in dynamic smem.
// ---------------------------------------------------------------------------
__global__ __launch_bounds__(128)
void attn_merge(const float* __restrict__ emb, const int* __restrict__ sidx,
                float* __restrict__ out)
{
    extern __shared__ float sm[];
    float* sqk   = sm;                 // 12288 floats (6 rows x 2048)
    float* ssc   = sm + 12288;         // 576 = 16 heads x 6 x 6
    float* swm   = ssc + 576;          // 36
    float* scon  = swm + 64;           // 8
    float* smask = scon + 8;           // 8
    int*   sidxs = (int*)(smask + 8);  // 8

    const int g = blockIdx.x;
    const int tid = threadIdx.x;

    const float4* src = (const float4*)(g_qk + (size_t)g * (6*2048));
    float4* d4 = (float4*)sqk;
    for (int i = tid; i < 3072; i += 128) d4[i] = src[i];

    if (tid < 6) {
        int v = __ldg(&sidx[g*6 + tid]);
        sidxs[tid] = v;
        smask[tid] = (tid == 0 || v != 0) ? 1.0f : 0.0f;
    }
    __syncthreads();

    // scores[h,i,j] = q_i(h).k_j(h)/8 + m_i*m_j
    for (int d0 = tid; d0 < 576; d0 += 128) {
        int h = d0 / 36; int p = d0 - h*36; int i = p / 6; int j = p - i*6;
        const float* qp = sqk + i*2048 + h*64;
        const float* kp = sqk + j*2048 + 1024 + h*64;
        float acc = 0.f;
        #pragma unroll
        for (int dd = 0; dd < 64; dd++) acc += qp[dd] * kp[dd];
        ssc[d0] = acc * 0.125f + smask[i] * smask[j];
    }
    __syncthreads();

    // softmax over j for each (h,i)  [96 rows]
    if (tid < 96) {
        float* r = ssc + tid*6;
        float mx = r[0];
        #pragma unroll
        for (int j = 1; j < 6; j++) mx = fmaxf(mx, r[j]);
        float e[6]; float sum = 0.f;
        #pragma unroll
        for (int j = 0; j < 6; j++) { e[j] = expf(r[j] - mx); sum += e[j]; }
        float inv = 1.0f / sum;
        #pragma unroll
        for (int j = 0; j < 6; j++) r[j] = e[j] * inv;
    }
    __syncthreads();

    // mean over heads
    if (tid < 36) {
        float s = 0.f;
        #pragma unroll
        for (int h = 0; h < 16; h++) s += ssc[h*36 + tid];
        swm[tid] = s * (1.0f/16.0f);
    }
    __syncthreads();

    // contrib[j] = m_j * sum_i m_i * wmean[i,j]
    if (tid < 6) {
        float cj = 0.f;
        #pragma unroll
        for (int i = 0; i < 6; i++) cj += smask[i] * swm[i*6 + tid];
        scon[tid] = cj * smask[tid];
    }
    __syncthreads();
    if (tid == 0) {
        float tot = 1e-8f;
        #pragma unroll
        for (int j = 0; j < 6; j++) tot += scon[j];
        float inv = 1.0f / tot;
        #pragma unroll
        for (int j = 0; j < 6; j++) scon[j] *= inv;
    }
    __syncthreads();

    // unified row -> out[b, idx0, :]
    int b = g >> 7;
    size_t baserow = (size_t)(b * Sc);
    float4* drow = (float4*)(out + (baserow + sidxs[0]) * (size_t)Hc);
    for (int c4 = tid; c4 < 256; c4 += 128) {
        float4 acc = make_float4(0.f, 0.f, 0.f, 0.f);
        #pragma unroll
        for (int k = 0; k < 6; k++) {
            float ck = scon[k];
            if (ck != 0.0f) {
                const float4 v =
                    ((const float4*)(emb + (baserow + sidxs[k]) * (size_t)Hc))[c4];
                acc.x += ck*v.x; acc.y += ck*v.y; acc.z += ck*v.z; acc.w += ck*v.w;
            }
        }
        drow[c4] = acc;
    }
}

// ---------------------------------------------------------------------------
extern "C" void kernel_launch(void* const* d_in, const int* in_sizes, int n_in,
                              void* d_out, int out_size)
{
    const float* emb  = (const float*)d_in[0];
    const float* wqk  = (const float*)d_in[1];
    const float* bias = (const float*)d_in[2];
    const int*   sidx = (const int*)d_in[3];
    float* out = (float*)d_out;

    dim3 gg(Nc/BN, Mc/BM);
    gemm_qk<<<gg, 256>>>(emb, wqk, bias, sidx);

    copy_zero<<<Bc*Sc, 256>>>(emb, sidx, out);

    int smem = (12288 + 576 + 64 + 8 + 8 + 8) * 4;
    cudaFuncSetAttribute(attn_merge, cudaFuncAttributeMaxDynamicSharedMemorySize, smem);
    attn_merge<<<Lc, 128, smem>>>(emb, sidx, out);
}

// round 3
// speedup vs baseline: 2.2521x; 2.2521x over previous
#include <cuda_runtime.h>
#include <cuda_fp16.h>
#include <cstdint>
#include <cstddef>

// Problem constants
#define Bc 32
#define Sc 1024
#define Hc 1024
#define Wc 128
#define Kc 6
#define Lc (Bc*Wc)        // 4096 groups
#define Mc (Lc*Kc)        // 24576 rows
#define Nc 2048           // q|k features

// ---------------- static device scratch (allocation-free) ------------------
// A tiled: [192 m-tiles * 32 k-tiles][128 rows x 64B, swizzled]  (fp16)
__device__ __align__(1024) __half g_A[(size_t)Mc * Hc];
// W tiled: [16 n-tiles * 32 k-tiles][128 rows x 64B, swizzled]   (fp16)
__device__ __align__(1024) __half g_W[(size_t)Nc * Hc];
// qk result, row-major fp16 [24576][2048]
__device__ __align__(1024) __half g_qkh[(size_t)Mc * Nc];

__device__ __forceinline__ uint32_t smem_u32(const void* p) {
    uint32_t a;
    asm("{ .reg .u64 t; cvta.to.shared.u64 t, %1; cvt.u32.u64 %0, t; }" : "=r"(a) : "l"(p));
    return a;
}

// ---------------- PTX wrappers -----------------------------------------
#define MBAR_INIT(addr, cnt) \
    asm volatile("mbarrier.init.shared.b64 [%0], %1;" :: "r"(addr), "r"(cnt) : "memory")
#define MBAR_EXPECT_TX(addr, bytes) \
    asm volatile("mbarrier.arrive.expect_tx.shared.b64 _, [%0], %1;" :: "r"(addr), "r"(bytes) : "memory")
#define MBAR_ARRIVE(addr) \
    asm volatile("mbarrier.arrive.shared.b64 _, [%0];" :: "r"(addr) : "memory")

__device__ __forceinline__ void mbar_wait(uint32_t mbar, uint32_t phase) {
    asm volatile(
        "{\n\t.reg .pred P;\n\t"
        "WL_%=:\n\t"
        "mbarrier.try_wait.parity.acquire.cta.shared::cta.b64 P, [%0], %1, 0x989680;\n\t"
        "@P bra.uni WD_%=;\n\t"
        "bra.uni WL_%=;\n\t"
        "WD_%=:\n\t}"
        :: "r"(mbar), "r"(phase) : "memory");
}

__device__ __forceinline__ void bulk_g2s(uint32_t dst, const void* src, uint32_t bytes, uint32_t mbar) {
    asm volatile(
        "cp.async.bulk.shared::cluster.global.mbarrier::complete_tx::bytes [%0], [%1], %2, [%3];"
        :: "r"(dst), "l"(src), "r"(bytes), "r"(mbar) : "memory");
}

#define LDMX4(r0, r1, r2, r3, addr) \
    asm volatile("ldmatrix.sync.aligned.m8n8.x4.shared.b16 {%0,%1,%2,%3}, [%4];" \
                 : "=r"(r0), "=r"(r1), "=r"(r2), "=r"(r3) : "r"(addr))

__device__ __forceinline__ void mma16816(float* c, const uint32_t* a, const uint32_t* b) {
    asm volatile(
        "mma.sync.aligned.m16n8k16.row.col.f32.f16.f16.f32 "
        "{%0,%1,%2,%3}, {%4,%5,%6,%7}, {%8,%9}, {%0,%1,%2,%3};\n"
        : "+f"(c[0]), "+f"(c[1]), "+f"(c[2]), "+f"(c[3])
        : "r"(a[0]), "r"(a[1]), "r"(a[2]), "r"(a[3]), "r"(b[0]), "r"(b[1]));
}

// swizzled byte offset within a [128 x 64B] tile for (row r, 16B-chunk c)
__device__ __forceinline__ uint32_t tswz(int r, int c) {
    return (uint32_t)(r * 64 + ((c ^ ((r >> 1) & 3)) << 4));
}

// ---------------------------------------------------------------------------
// conv_w: fp32 W[0:2048][1024] -> fp16 tiled+swizzled g_W
// tile id = nt*32 + kt, tile = 128 rows (n) x 64B (32 k fp16)
// ---------------------------------------------------------------------------
__global__ __launch_bounds__(128)
void conv_w(const float* __restrict__ wqk)
{
    int n = blockIdx.x;           // 0..2047
    int tid = threadIdx.x;        // 0..127 -> 8 floats each
    int c0 = tid * 8;
    int nt = n >> 7, r = n & 127, kt = tid >> 2, c = tid & 3;
    const float* src = wqk + (size_t)n * Hc + c0;
    float4 v0 = *(const float4*)src;
    float4 v1 = *(const float4*)(src + 4);
    __half2 h[4];
    h[0] = __floats2half2_rn(v0.x, v0.y);
    h[1] = __floats2half2_rn(v0.z, v0.w);
    h[2] = __floats2half2_rn(v1.x, v1.y);
    h[3] = __floats2half2_rn(v1.z, v1.w);
    char* dst = (char*)g_W + ((size_t)(nt * 32 + kt)) * 8192 + tswz(r, c);
    *(uint4*)dst = *(uint4*)h;
}

// ---------------------------------------------------------------------------
// conv_a: gather + mask + fp32->fp16 into tiled+swizzled g_A
// ---------------------------------------------------------------------------
__global__ __launch_bounds__(128)
void conv_a(const float* __restrict__ emb, const int* __restrict__ sidx)
{
    int m = blockIdx.x;           // 0..24575
    int tid = threadIdx.x;
    int g = m / 6, kk = m - g * 6;
    int idx = __ldg(&sidx[m]);
    int b = g >> 7;
    bool valid = (kk == 0) || (idx != 0);
    int c0 = tid * 8;
    int mt = m >> 7, r = m & 127, kt = tid >> 2, c = tid & 3;
    uint4 out = make_uint4(0u, 0u, 0u, 0u);
    if (valid) {
        const float* src = emb + ((size_t)(b * Sc + idx)) * Hc + c0;
        float4 v0 = *(const float4*)src;
        float4 v1 = *(const float4*)(src + 4);
        __half2 h[4];
        h[0] = __floats2half2_rn(v0.x, v0.y);
        h[1] = __floats2half2_rn(v0.z, v0.w);
        h[2] = __floats2half2_rn(v1.x, v1.y);
        h[3] = __floats2half2_rn(v1.z, v1.w);
        out = *(uint4*)h;
    }
    char* dst = (char*)g_A + ((size_t)(mt * 32 + kt)) * 8192 + tswz(r, c);
    *(uint4*)dst = out;
}

// ---------------------------------------------------------------------------
// GEMM: qk = A(fp16) . W(fp16)^T + bias  -> fp16
// M=24576, N=2048, K=1024. CTA 128x128, BK=32, 4-stage cp.async.bulk pipeline,
// mma.sync m16n8k16, ldmatrix feeds. 256 threads, warps 4(m) x 2(n).
// ---------------------------------------------------------------------------
#define A_TILE 8192
#define B_TILE 8192
#define STG_B  (A_TILE + B_TILE)
#define NSTG   4
#define KT     32
#define SMEM_TOT (NSTG*STG_B + 128)   // 65664

__global__ __launch_bounds__(256, 2)
void gemm_qk(const float* __restrict__ bias)
{
    extern __shared__ char smem[];
    const uint32_t sb = smem_u32(smem);
    const uint32_t mb_full = sb + NSTG * STG_B;       // 4 x 8B
    const uint32_t mb_free = mb_full + 32;            // 4 x 8B

    const int tid = threadIdx.x;
    const int wid = tid >> 5, lane = tid & 31;
    const int bx = blockIdx.x;   // n tile 0..15
    const int by = blockIdx.y;   // m tile 0..191

    if (tid == 0) {
        #pragma unroll
        for (int s = 0; s < NSTG; s++) {
            MBAR_INIT(mb_full + 8 * s, 1);
            MBAR_INIT(mb_free + 8 * s, 8);
        }
    }
    __syncthreads();

    const char* Abase = (const char*)g_A + (size_t)by * KT * A_TILE;
    const char* Bbase = (const char*)g_W + (size_t)bx * KT * B_TILE;

    // producer: prime 4 stages
    if (tid == 0) {
        #pragma unroll
        for (int s = 0; s < NSTG; s++) {
            MBAR_EXPECT_TX(mb_full + 8 * s, STG_B);
            bulk_g2s(sb + s * STG_B,          Abase + (size_t)s * A_TILE, A_TILE, mb_full + 8 * s);
            bulk_g2s(sb + s * STG_B + A_TILE, Bbase + (size_t)s * B_TILE, B_TILE, mb_full + 8 * s);
        }
    }

    // fragment addressing (per thread, constant across stages)
    const int warp_m = wid & 3;
    const int warp_n = wid >> 2;
    const int rA0 = warp_m * 32 + (lane & 15);
    const int rA1 = rA0 + 16;
    const uint32_t aoff0 = (uint32_t)(rA0 * 64); const int swA0 = (rA0 >> 1) & 3;
    const uint32_t aoff1 = (uint32_t)(rA1 * 64); const int swA1 = (rA1 >> 1) & 3;
    const int cidA = lane >> 4;
    const int rBb = warp_n * 64 + ((lane >> 4) & 1) * 8 + (lane & 7);
    const int cidB = (lane >> 3) & 1;
    uint32_t boff[4]; int swB[4];
    #pragma unroll
    for (int np = 0; np < 4; np++) {
        int r = rBb + np * 16;
        boff[np] = (uint32_t)(r * 64);
        swB[np] = (r >> 1) & 3;
    }

    float c[2][8][4];
    #pragma unroll
    for (int i = 0; i < 2; i++)
        #pragma unroll
        for (int j = 0; j < 8; j++)
            #pragma unroll
            for (int q = 0; q < 4; q++) c[i][j][q] = 0.f;

    for (int kt = 0; kt < KT; kt++) {
        const int s = kt & (NSTG - 1);
        const uint32_t ph = (kt >> 2) & 1;
        mbar_wait(mb_full + 8 * s, ph);

        const uint32_t Ab = sb + s * STG_B;
        const uint32_t Bb = Ab + A_TILE;
        #pragma unroll
        for (int ks = 0; ks < 2; ks++) {
            const int kc = ks * 2;
            uint32_t a0[4], a1[4], b[4][4];
            LDMX4(a0[0], a0[1], a0[2], a0[3], Ab + aoff0 + (((kc + cidA) ^ swA0) << 4));
            LDMX4(a1[0], a1[1], a1[2], a1[3], Ab + aoff1 + (((kc + cidA) ^ swA1) << 4));
            #pragma unroll
            for (int np = 0; np < 4; np++)
                LDMX4(b[np][0], b[np][1], b[np][2], b[np][3],
                      Bb + boff[np] + (((kc + cidB) ^ swB[np]) << 4));
            #pragma unroll
            for (int nf = 0; nf < 8; nf++) {
                mma16816(c[0][nf], a0, &b[nf >> 1][(nf & 1) * 2]);
                mma16816(c[1][nf], a1, &b[nf >> 1][(nf & 1) * 2]);
            }
        }
        if (lane == 0) MBAR_ARRIVE(mb_free + 8 * s);

        if (tid == 0 && kt + NSTG < KT) {
            mbar_wait(mb_free + 8 * s, (kt >> 2) & 1);
            MBAR_EXPECT_TX(mb_full + 8 * s, STG_B);
            bulk_g2s(sb + s * STG_B,          Abase + (size_t)(kt + NSTG) * A_TILE, A_TILE, mb_full + 8 * s);
            bulk_g2s(sb + s * STG_B + A_TILE, Bbase + (size_t)(kt + NSTG) * B_TILE, B_TILE, mb_full + 8 * s);
        }
    }

    // epilogue: +bias -> fp16 -> g_qkh
    const int gid = lane >> 2, tig = lane & 3;
    #pragma unroll
    for (int mf = 0; mf < 2; mf++) {
        #pragma unroll
        for (int nf = 0; nf < 8; nf++) {
            int row = by * 128 + warp_m * 32 + mf * 16 + gid;
            int col = bx * 128 + warp_n * 64 + nf * 8 + tig * 2;
            float2 bv = *(const float2*)&bias[col];
            __half2 h0 = __floats2half2_rn(c[mf][nf][0] + bv.x, c[mf][nf][1] + bv.y);
            __half2 h1 = __floats2half2_rn(c[mf][nf][2] + bv.x, c[mf][nf][3] + bv.y);
            *(__half2*)&g_qkh[(size_t)row * Nc + col]       = h0;
            *(__half2*)&g_qkh[(size_t)(row + 8) * Nc + col] = h1;
        }
    }
}

// ---------------------------------------------------------------------------
// Copy/zero pass over the output
// ---------------------------------------------------------------------------
__global__ __launch_bounds__(256)
void copy_zero(const float* __restrict__ emb, const int* __restrict__ sidx,
               float* __restrict__ out)
{
    int row = blockIdx.x;        // 0 .. B*S-1
    int b = row >> 10;
    int s = row & 1023;
    int w = s >> 3;
    int k = s & 7;
    int zero = 0;
    if (k >= 1 && k < 6) {
        int iv = __ldg(&sidx[(b * Wc + w) * Kc + k]);
        zero = (iv != 0);
    }
    const float4* src = (const float4*)(emb + (size_t)row * Hc);
    float4* dst = (float4*)(out + (size_t)row * Hc);
    float4 v = src[threadIdx.x];
    if (zero) v = make_float4(0.f, 0.f, 0.f, 0.f);
    dst[threadIdx.x] = v;
}

// ---------------------------------------------------------------------------
// Attention + merge: one block per group, fp16 qk slab (24KB contiguous)
// ---------------------------------------------------------------------------
__global__ __launch_bounds__(256)
void attn_merge(const float* __restrict__ emb, const int* __restrict__ sidx,
                float* __restrict__ out)
{
    __shared__ uint32_t sqk[6144];     // 6 rows x 1024 half2 (q|k)
    __shared__ float ssc[576];
    __shared__ float swm[64];
    __shared__ float scon[8];
    __shared__ float smask[8];
    __shared__ int sidxs[8];

    const int g = blockIdx.x;
    const int tid = threadIdx.x;

    const uint4* src = (const uint4*)(g_qkh + (size_t)g * (6 * 2048));
    uint4* d4 = (uint4*)sqk;
    for (int i = tid; i < 1536; i += 256) d4[i] = src[i];

    if (tid < 6) {
        int v = __ldg(&sidx[g * 6 + tid]);
        sidxs[tid] = v;
        smask[tid] = (tid == 0 || v != 0) ? 1.0f : 0.0f;
    }
    __syncthreads();

    // scores[h,i,j] = q_i(h).k_j(h)/8 + m_i*m_j
    for (int d0 = tid; d0 < 576; d0 += 256) {
        int h = d0 / 36; int p = d0 - h * 36; int i = p / 6; int j = p - i * 6;
        const uint32_t* qp = sqk + i * 1024 + h * 32;
        const uint32_t* kp = sqk + j * 1024 + 512 + h * 32;
        float acc = 0.f;
        #pragma unroll
        for (int dd = 0; dd < 32; dd++) {
            float2 q2 = __half22float2(*(const __half2*)&qp[dd]);
            float2 k2 = __half22float2(*(const __half2*)&kp[dd]);
            acc = fmaf(q2.x, k2.x, acc);
            acc = fmaf(q2.y, k2.y, acc);
        }
        ssc[d0] = acc * 0.125f + smask[i] * smask[j];
    }
    __syncthreads();

    if (tid < 96) {
        float* r = ssc + tid * 6;
        float mx = r[0];
        #pragma unroll
        for (int j = 1; j < 6; j++) mx = fmaxf(mx, r[j]);
        float e[6]; float sum = 0.f;
        #pragma unroll
        for (int j = 0; j < 6; j++) { e[j] = expf(r[j] - mx); sum += e[j]; }
        float inv = 1.0f / sum;
        #pragma unroll
        for (int j = 0; j < 6; j++) r[j] = e[j] * inv;
    }
    __syncthreads();

    if (tid < 36) {
        float s = 0.f;
        #pragma unroll
        for (int h = 0; h < 16; h++) s += ssc[h * 36 + tid];
        swm[tid] = s * (1.0f / 16.0f);
    }
    __syncthreads();

    if (tid < 6) {
        float cj = 0.f;
        #pragma unroll
        for (int i = 0; i < 6; i++) cj += smask[i] * swm[i * 6 + tid];
        scon[tid] = cj * smask[tid];
    }
    __syncthreads();
    if (tid == 0) {
        float tot = 1e-8f;
        #pragma unroll
        for (int j = 0; j < 6; j++) tot += scon[j];
        float inv = 1.0f / tot;
        #pragma unroll
        for (int j = 0; j < 6; j++) scon[j] *= inv;
    }
    __syncthreads();

    int b = g >> 7;
    size_t baserow = (size_t)(b * Sc);
    float4* drow = (float4*)(out + (baserow + sidxs[0]) * (size_t)Hc);
    for (int c4 = tid; c4 < 256; c4 += 256) {
        float4 acc = make_float4(0.f, 0.f, 0.f, 0.f);
        #pragma unroll
        for (int k = 0; k < 6; k++) {
            float ck = scon[k];
            if (ck != 0.0f) {
                const float4 v =
                    ((const float4*)(emb + (baserow + sidxs[k]) * (size_t)Hc))[c4];
                acc.x += ck * v.x; acc.y += ck * v.y; acc.z += ck * v.z; acc.w += ck * v.w;
            }
        }
        drow[c4] = acc;
    }
}

// ---------------------------------------------------------------------------
extern "C" void kernel_launch(void* const* d_in, const int* in_sizes, int n_in,
                              void* d_out, int out_size)
{
    const float* emb  = (const float*)d_in[0];
    const float* wqk  = (const float*)d_in[1];
    const float* bias = (const float*)d_in[2];
    const int*   sidx = (const int*)d_in[3];
    float* out = (float*)d_out;

    conv_w<<<Nc, 128>>>(wqk);
    conv_a<<<Mc, 128>>>(emb, sidx);

    cudaFuncSetAttribute(gemm_qk, cudaFuncAttributeMaxDynamicSharedMemorySize, SMEM_TOT);
    dim3 gg(16, 192);
    gemm_qk<<<gg, 256, SMEM_TOT>>>(bias);

    copy_zero<<<Bc * Sc, 256>>>(emb, sidx, out);

    attn_merge<<<Lc, 256>>>(emb, sidx, out);
}